// round 6
// baseline (speedup 1.0000x reference)
#include <cuda_runtime.h>
#include <cuda_bf16.h>
#include <cstdint>

// MultiDepthLimitedMSELoss: per-row greedy matching of 8 outputs to 8 targets
// (sequential argmin of |out - t_i|, matched output removed), then mean of
// squared matched distances; targets == 0.0 contribute exactly 0.
//
// One lane per row-PAIR (R=2 interleaved independent rows per thread, for
// ILP: a single matching chain is ~250 dependent cycles for ~170 instrs, so
// one chain/thread left the alu pipe at 67.7% and issue at 53.7%).
//
// argmin via packed integer keys over the LIVE set:
//   key_j = (bits(o_j - t_i) & 0x7FFFFFF8) | j    (one LOP3; j = live pos)
// Unsigned min gives min |distance| (3 lsb truncated, ~5e-7 rel err) AND the
// first-min live position (jnp.argmin tie-break preserved: compaction keeps
// order). Winner REMOVED by register-array compaction. Exactly-one-removal is
// structural (index bits make keys unique).
//
// Reduction fused via last-block pattern (threadfence + atomic counter,
// fixed-order double sum; deterministic, graph-replay safe, self-resetting).

#define BLOCKS   (148 * 8)    // 1184
#define THREADS  256
#define R        2            // rows per thread per iteration

__device__ float    g_partials[BLOCKS];
__device__ unsigned g_count = 0;

__global__ void __launch_bounds__(THREADS)
match_loss_kernel(const float* __restrict__ outs,
                  const float* __restrict__ tgts,
                  float* __restrict__ result,
                  int n)  // n = number of rows
{
    const unsigned FULL = 0xffffffffu;
    const int tid     = blockIdx.x * THREADS + threadIdx.x;
    const int nthread = gridDim.x * THREADS;

    float acc = 0.0f;

    for (int base = tid; base < n; base += nthread * R) {
        float o[R][8];
        float t[R][8];

        // ---- load R rows up-front (MLP: up to 8 LDG.128 in flight) ----
#pragma unroll
        for (int r = 0; r < R; ++r) {
            const int row = base + r * nthread;
            if (row < n) {
                const size_t b = (size_t)row << 3;
                const float4 o0 = __ldcs(reinterpret_cast<const float4*>(outs + b));
                const float4 o1 = __ldcs(reinterpret_cast<const float4*>(outs + b + 4));
                const float4 t0 = __ldcs(reinterpret_cast<const float4*>(tgts + b));
                const float4 t1 = __ldcs(reinterpret_cast<const float4*>(tgts + b + 4));
                o[r][0]=o0.x; o[r][1]=o0.y; o[r][2]=o0.z; o[r][3]=o0.w;
                o[r][4]=o1.x; o[r][5]=o1.y; o[r][6]=o1.z; o[r][7]=o1.w;
                t[r][0]=t0.x; t[r][1]=t0.y; t[r][2]=t0.z; t[r][3]=t0.w;
                t[r][4]=t1.x; t[r][5]=t1.y; t[r][6]=t1.z; t[r][7]=t1.w;
            } else {
#pragma unroll
                for (int j = 0; j < 8; ++j) { o[r][j] = 0.0f; t[r][j] = 0.0f; }
                // t == 0 -> every step contributes exactly 0
            }
        }

        // ---- 8 greedy matching steps, R chains interleaved ----
#pragma unroll
        for (int i = 0; i < 8; ++i) {
            const int k = 8 - i;               // live count (compile-time)
#pragma unroll
            for (int r = 0; r < R; ++r) {
                const float ti = t[r][i];

                unsigned kk[8];
#pragma unroll
                for (int j = 0; j < k; ++j)
                    kk[j] = (__float_as_uint(o[r][j] - ti) & 0x7FFFFFF8u)
                            | (unsigned)j;

                // balanced min tree over k keys
#pragma unroll
                for (int s = 1; s < k; s <<= 1) {
#pragma unroll
                    for (int j = 0; j + s < k; j += (s << 1))
                        kk[j] = min(kk[j], kk[j + s]);
                }
                const unsigned m = kk[0];
                const int w = (int)(m & 7u);   // winning live position

                const float bd  = __uint_as_float(m & 0x7FFFFFF8u);
                const float bd2 = (ti != 0.0f) ? bd : 0.0f;
                acc = fmaf(bd2, bd2, acc);

                // compact: remove live position w (order preserved)
#pragma unroll
                for (int j = 0; j < k - 1; ++j)
                    o[r][j] = (j < w) ? o[r][j] : o[r][j + 1];
            }
        }
    }

    // ---- warp + block reduction (fixed order, deterministic) ----
#pragma unroll
    for (int s = 16; s > 0; s >>= 1)
        acc += __shfl_xor_sync(FULL, acc, s);

    __shared__ float sw[THREADS / 32];
    __shared__ bool  isLast;
    const int lane = threadIdx.x & 31;
    const int wib  = threadIdx.x >> 5;
    if (lane == 0) sw[wib] = acc;
    __syncthreads();
    if (threadIdx.x == 0) {
        float b = 0.0f;
#pragma unroll
        for (int i = 0; i < THREADS / 32; ++i) b += sw[i];
        g_partials[blockIdx.x] = b;
        __threadfence();
        const unsigned prev = atomicAdd(&g_count, 1u);
        isLast = (prev == (unsigned)(gridDim.x - 1));
    }
    __syncthreads();

    // ---- last block finishes: fixed-order double sum over partials ----
    if (isLast) {
        __shared__ double sm[THREADS];
        double s = 0.0;
        for (int i = threadIdx.x; i < BLOCKS; i += THREADS)
            s += (double)g_partials[i];
        sm[threadIdx.x] = s;
        __syncthreads();
#pragma unroll
        for (int st = THREADS / 2; st > 0; st >>= 1) {
            if (threadIdx.x < st) sm[threadIdx.x] += sm[threadIdx.x + st];
            __syncthreads();
        }
        if (threadIdx.x == 0) {
            result[0] = (float)(sm[0] / ((double)n * 8.0));
            g_count = 0;   // reset for next graph replay
        }
    }
}

extern "C" void kernel_launch(void* const* d_in, const int* in_sizes, int n_in,
                              void* d_out, int out_size)
{
    const float* outputs = (const float*)d_in[0];
    const float* targets = (const float*)d_in[1];
    const int n = in_sizes[0] / 8;   // rows

    match_loss_kernel<<<BLOCKS, THREADS>>>(outputs, targets, (float*)d_out, n);
}

// round 13
// speedup vs baseline: 1.0044x; 1.0044x over previous
#include <cuda_runtime.h>
#include <cuda_bf16.h>
#include <cstdint>

// MultiDepthLimitedMSELoss: per-row greedy matching of 8 outputs to 8 targets
// (sequential argmin of |out - t_i|, matched output removed), then mean of
// squared matched distances; targets == 0.0 contribute exactly 0.
//
// One lane per row (R=2 ILP regressed in round 6: occupancy loss, no issue
// gain). argmin via packed integer keys over the LIVE set:
//   key_j = (bits(o_j - t_i) & 0x7FFFFFF8) | j   (one LOP3: abs+trunc+index)
// Unsigned min gives min |distance| AND first-min live position (jnp.argmin
// tie-break preserved: compaction keeps order). Winner REMOVED by register
// compaction; exactly-one-removal is structural (index bits unique).
// Distance reused directly as as_float(m) WITH index bits in the 3 lsb
// (err <= 7 ulp ~ 2^-20 rel, invisible vs the 3-bit truncation already
// accepted at rel_err 5e-7).
//
// Software-pipelined 2-deep: next row's 4x LDG.128 issued before processing
// the current row, overlapping DRAM latency with the ~400cyc matching chain
// (issue was 53.7% with loads exposed at each iteration head).
//
// Reduction fused via last-block pattern (threadfence + atomic counter,
// fixed-order double sum; deterministic, graph-replay safe, self-resetting).

#define BLOCKS   (148 * 10)   // 1480 (round-5 proven)
#define THREADS  256

__device__ float    g_partials[BLOCKS];
__device__ unsigned g_count = 0;

struct Row8 { float o[8]; float t[8]; };

__device__ __forceinline__
void load_row(Row8& R, const float* __restrict__ outs,
              const float* __restrict__ tgts, int row, int n)
{
    if (row < n) {
        const size_t b = (size_t)row << 3;
        const float4 o0 = __ldcs(reinterpret_cast<const float4*>(outs + b));
        const float4 o1 = __ldcs(reinterpret_cast<const float4*>(outs + b + 4));
        const float4 t0 = __ldcs(reinterpret_cast<const float4*>(tgts + b));
        const float4 t1 = __ldcs(reinterpret_cast<const float4*>(tgts + b + 4));
        R.o[0]=o0.x; R.o[1]=o0.y; R.o[2]=o0.z; R.o[3]=o0.w;
        R.o[4]=o1.x; R.o[5]=o1.y; R.o[6]=o1.z; R.o[7]=o1.w;
        R.t[0]=t0.x; R.t[1]=t0.y; R.t[2]=t0.z; R.t[3]=t0.w;
        R.t[4]=t1.x; R.t[5]=t1.y; R.t[6]=t1.z; R.t[7]=t1.w;
    } else {
#pragma unroll
        for (int j = 0; j < 8; ++j) { R.o[j] = 0.0f; R.t[j] = 0.0f; }
        // t == 0 -> every step contributes exactly 0
    }
}

__device__ __forceinline__
void process_row(Row8& R, float& acc)
{
#pragma unroll
    for (int i = 0; i < 8; ++i) {
        const int k = 8 - i;               // live count (compile-time)
        const float ti = R.t[i];

        unsigned kk[8];
#pragma unroll
        for (int j = 0; j < k; ++j)
            kk[j] = (__float_as_uint(R.o[j] - ti) & 0x7FFFFFF8u) | (unsigned)j;

        // balanced min tree over k keys (in place)
#pragma unroll
        for (int s = 1; s < k; s <<= 1) {
#pragma unroll
            for (int j = 0; j + s < k; j += (s << 1))
                kk[j] = min(kk[j], kk[j + s]);
        }
        const unsigned m = kk[0];

        if (k > 1) {
            const int w = (int)(m & 7u);   // winning live position
            // compact: remove live position w (order preserved)
#pragma unroll
            for (int j = 0; j < k - 1; ++j)
                R.o[j] = (j < w) ? R.o[j] : R.o[j + 1];
        }

        // |d| with index bits still in the 3 lsb: <= 7 ulp error
        const float bd = __uint_as_float(m);
        if (ti != 0.0f)                    // IGNORE_VALUE == 0.0
            acc = fmaf(bd, bd, acc);
    }
}

__global__ void __launch_bounds__(THREADS)
match_loss_kernel(const float* __restrict__ outs,
                  const float* __restrict__ tgts,
                  float* __restrict__ result,
                  int n)  // n = number of rows
{
    const unsigned FULL = 0xffffffffu;
    const int tid    = blockIdx.x * THREADS + threadIdx.x;
    const int stride = BLOCKS * THREADS;

    float acc = 0.0f;

    Row8 A, B;
    load_row(A, outs, tgts, tid, n);
    for (int r = tid; r < n; r += 2 * stride) {
        load_row(B, outs, tgts, r + stride, n);       // prefetch while A hot
        process_row(A, acc);
        load_row(A, outs, tgts, r + 2 * stride, n);   // prefetch while B hot
        process_row(B, acc);
    }

    // ---- warp + block reduction (fixed order, deterministic) ----
#pragma unroll
    for (int s = 16; s > 0; s >>= 1)
        acc += __shfl_xor_sync(FULL, acc, s);

    __shared__ float sw[THREADS / 32];
    __shared__ bool  isLast;
    const int lane = threadIdx.x & 31;
    const int wib  = threadIdx.x >> 5;
    if (lane == 0) sw[wib] = acc;
    __syncthreads();
    if (threadIdx.x == 0) {
        float b = 0.0f;
#pragma unroll
        for (int i = 0; i < THREADS / 32; ++i) b += sw[i];
        g_partials[blockIdx.x] = b;
        __threadfence();
        const unsigned prev = atomicAdd(&g_count, 1u);
        isLast = (prev == (unsigned)(gridDim.x - 1));
    }
    __syncthreads();

    // ---- last block finishes: fixed-order double sum over partials ----
    if (isLast) {
        __shared__ double sm[THREADS];
        double s = 0.0;
        for (int i = threadIdx.x; i < BLOCKS; i += THREADS)
            s += (double)g_partials[i];
        sm[threadIdx.x] = s;
        __syncthreads();
#pragma unroll
        for (int st = THREADS / 2; st > 0; st >>= 1) {
            if (threadIdx.x < st) sm[threadIdx.x] += sm[threadIdx.x + st];
            __syncthreads();
        }
        if (threadIdx.x == 0) {
            result[0] = (float)(sm[0] / ((double)n * 8.0));
            g_count = 0;   // reset for next graph replay
        }
    }
}

extern "C" void kernel_launch(void* const* d_in, const int* in_sizes, int n_in,
                              void* d_out, int out_size)
{
    const float* outputs = (const float*)d_in[0];
    const float* targets = (const float*)d_in[1];
    const int n = in_sizes[0] / 8;   // rows

    match_loss_kernel<<<BLOCKS, THREADS>>>(outputs, targets, (float*)d_out, n);
}

// round 17
// speedup vs baseline: 1.1266x; 1.1217x over previous
#include <cuda_runtime.h>
#include <cuda_bf16.h>
#include <cstdint>

// MultiDepthLimitedMSELoss: per-row greedy matching of 8 outputs to 8 targets
// (sequential argmin of |out - t_i|, matched output removed), then mean of
// squared matched distances; targets == 0.0 contribute exactly 0.
//
// One lane per row. argmin via packed integer keys over the LIVE set:
//   key_j = (bits(o_j - t_i) & 0x7FFFFFF8) | j   (one LOP3: abs+trunc+index)
// Unsigned min gives min |distance| AND first-min live position (jnp.argmin
// tie-break preserved: compaction keeps order). Winner REMOVED by register
// compaction; exactly-one-removal is structural (index bits unique).
// Distance reused as as_float(m) WITH index bits in the 3 lsb (<=7 ulp err,
// invisible vs the accepted 3-bit truncation; measured rel_err 4.0e-7).
//
// Round-13 lessons applied:
//  - software pipelining REVERTED: ptxas re-sank the prefetches (regs stayed
//    32), issue% unchanged, dur regressed 55.8 -> 57.8us.
//  - grid = EXACTLY one wave: regs=32 -> 8 blocks/SM -> 1184 blocks; the old
//    1480-block grid ran a 296-block straggler wave (achieved occ 75.6%).
//
// Reduction fused via last-block pattern (threadfence + atomic counter,
// fixed-order double sum; deterministic, graph-replay safe, self-resetting).

#define BLOCKS   (148 * 8)    // 1184 = exactly one wave at 8 blocks/SM
#define THREADS  256

__device__ float    g_partials[BLOCKS];
__device__ unsigned g_count = 0;

__global__ void __launch_bounds__(THREADS, 8)
match_loss_kernel(const float* __restrict__ outs,
                  const float* __restrict__ tgts,
                  float* __restrict__ result,
                  int n)  // n = number of rows
{
    const unsigned FULL = 0xffffffffu;
    const int tid    = blockIdx.x * THREADS + threadIdx.x;
    const int stride = BLOCKS * THREADS;

    float acc = 0.0f;

    for (int row = tid; row < n; row += stride) {
        const size_t b = (size_t)row << 3;   // row * 8 floats
        // streaming loads (no reuse); warp covers 1024 contiguous B per tensor
        const float4 o0 = __ldcs(reinterpret_cast<const float4*>(outs + b));
        const float4 o1 = __ldcs(reinterpret_cast<const float4*>(outs + b + 4));
        const float4 t0 = __ldcs(reinterpret_cast<const float4*>(tgts + b));
        const float4 t1 = __ldcs(reinterpret_cast<const float4*>(tgts + b + 4));

        float o[8] = { o0.x, o0.y, o0.z, o0.w, o1.x, o1.y, o1.z, o1.w };
        const float t[8] = { t0.x, t0.y, t0.z, t0.w, t1.x, t1.y, t1.z, t1.w };

#pragma unroll
        for (int i = 0; i < 8; ++i) {
            const int k = 8 - i;               // live count (compile-time)
            const float ti = t[i];

            unsigned kk[8];
#pragma unroll
            for (int j = 0; j < k; ++j)
                kk[j] = (__float_as_uint(o[j] - ti) & 0x7FFFFFF8u) | (unsigned)j;

            // balanced min tree over k keys (in place)
#pragma unroll
            for (int s = 1; s < k; s <<= 1) {
#pragma unroll
                for (int j = 0; j + s < k; j += (s << 1))
                    kk[j] = min(kk[j], kk[j + s]);
            }
            const unsigned m = kk[0];

            if (k > 1) {
                const int w = (int)(m & 7u);   // winning live position
                // compact: remove live position w (order preserved)
#pragma unroll
                for (int j = 0; j < k - 1; ++j)
                    o[j] = (j < w) ? o[j] : o[j + 1];
            }

            // |d| with index bits still in the 3 lsb: <= 7 ulp error
            const float bd = __uint_as_float(m);
            if (ti != 0.0f)                    // IGNORE_VALUE == 0.0
                acc = fmaf(bd, bd, acc);
        }
    }

    // ---- warp + block reduction (fixed order, deterministic) ----
#pragma unroll
    for (int s = 16; s > 0; s >>= 1)
        acc += __shfl_xor_sync(FULL, acc, s);

    __shared__ float sw[THREADS / 32];
    __shared__ bool  isLast;
    const int lane = threadIdx.x & 31;
    const int wib  = threadIdx.x >> 5;
    if (lane == 0) sw[wib] = acc;
    __syncthreads();
    if (threadIdx.x == 0) {
        float b = 0.0f;
#pragma unroll
        for (int i = 0; i < THREADS / 32; ++i) b += sw[i];
        g_partials[blockIdx.x] = b;
        __threadfence();
        const unsigned prev = atomicAdd(&g_count, 1u);
        isLast = (prev == (unsigned)(gridDim.x - 1));
    }
    __syncthreads();

    // ---- last block finishes: fixed-order double sum over partials ----
    if (isLast) {
        __shared__ double sm[THREADS];
        double s = 0.0;
        for (int i = threadIdx.x; i < BLOCKS; i += THREADS)
            s += (double)g_partials[i];
        sm[threadIdx.x] = s;
        __syncthreads();
#pragma unroll
        for (int st = THREADS / 2; st > 0; st >>= 1) {
            if (threadIdx.x < st) sm[threadIdx.x] += sm[threadIdx.x + st];
            __syncthreads();
        }
        if (threadIdx.x == 0) {
            result[0] = (float)(sm[0] / ((double)n * 8.0));
            g_count = 0;   // reset for next graph replay
        }
    }
}

extern "C" void kernel_launch(void* const* d_in, const int* in_sizes, int n_in,
                              void* d_out, int out_size)
{
    const float* outputs = (const float*)d_in[0];
    const float* targets = (const float*)d_in[1];
    const int n = in_sizes[0] / 8;   // rows

    match_loss_kernel<<<BLOCKS, THREADS>>>(outputs, targets, (float*)d_out, n);
}